// round 13
// baseline (speedup 1.0000x reference)
#include <cuda_runtime.h>
#include <cuda_fp16.h>
#include <cstdint>
#include <cstddef>

// Shapes: B=64, T=128, D=512, H=512, C=4096, 4C=16384, L=2, DIRS=2
// d_out packing (float32): seq [2,64,128,1024] | hs [2,64,1024] | cs [2,64,8192]
#define SEQ_OFF   0ull
#define HS_OFF    16777216ull
#define CS_OFF    16908288ull

// ------------------------- device scratch (all GEMM operands fp16) -------------------------
__device__ __align__(16) __half g_xprojH[2ull*8192ull*16384ull]; // 512 MB [dir][b*128+t][np]
__device__ __align__(16) __half g_WiH[4ull*16384ull*512ull];     // [ld][np][k], np=c*4+g
__device__ __align__(16) __half g_WhH[4ull*16384ull*512ull];
__device__ __align__(16) __half g_WpH[4ull*512ull*4096ull];      // [ld][h][c]
__device__ __align__(16) __half g_xH[8192ull*512ull];            // x as fp16
__device__ __align__(16) __half g_y0H[2ull*8192ull*512ull];      // layer-0 outputs (fp16)
__device__ __align__(16) __half g_aH[2*64*4096];                 // o*tanh(c) (fp16)
__device__ __align__(16) __half g_hH[2*64*512];                  // hidden state (fp16)
__device__ float g_c[2*64*4096];                                 // cell state fp32
__device__ float g_bQ[4*16384];                                  // interleaved bias fp32

// ------------------------- helpers -------------------------
__device__ __forceinline__ void mmah(float* c, const uint32_t* a, const uint32_t* b) {
    asm volatile(
        "mma.sync.aligned.m16n8k16.row.col.f32.f16.f16.f32 "
        "{%0,%1,%2,%3}, {%4,%5,%6,%7}, {%8,%9}, {%0,%1,%2,%3};\n"
        : "+f"(c[0]), "+f"(c[1]), "+f"(c[2]), "+f"(c[3])
        : "r"(a[0]), "r"(a[1]), "r"(a[2]), "r"(a[3]), "r"(b[0]), "r"(b[1]));
}
// warp-collective ldmatrix: 4 / 2 8x8 b16 tiles, per-lane row address
__device__ __forceinline__ void ldsm4(uint32_t& r0, uint32_t& r1, uint32_t& r2, uint32_t& r3,
                                      const uint32_t* p) {
    uint32_t a = (uint32_t)__cvta_generic_to_shared(p);
    asm volatile("ldmatrix.sync.aligned.m8n8.x4.shared.b16 {%0,%1,%2,%3}, [%4];"
                 : "=r"(r0), "=r"(r1), "=r"(r2), "=r"(r3) : "r"(a));
}
__device__ __forceinline__ void ldsm2(uint32_t& r0, uint32_t& r1, const uint32_t* p) {
    uint32_t a = (uint32_t)__cvta_generic_to_shared(p);
    asm volatile("ldmatrix.sync.aligned.m8n8.x2.shared.b16 {%0,%1}, [%2];"
                 : "=r"(r0), "=r"(r1) : "r"(a));
}
__device__ __forceinline__ void cp16(void* smem, const void* g) {
    uint32_t s = (uint32_t)__cvta_generic_to_shared(smem);
    asm volatile("cp.async.cg.shared.global [%0], [%1], 16;\n" :: "r"(s), "l"(g));
}
__device__ __forceinline__ uint64_t mk_evict_last() {
    uint64_t p;
    asm("createpolicy.fractional.L2::evict_last.b64 %0, 1.0;" : "=l"(p));
    return p;
}
__device__ __forceinline__ void cp16_el(void* smem, const void* g, uint64_t pol) {
    uint32_t s = (uint32_t)__cvta_generic_to_shared(smem);
    asm volatile("cp.async.cg.shared.global.L2::cache_hint [%0], [%1], 16, %2;\n"
                 :: "r"(s), "l"(g), "l"(pol));
}
__device__ __forceinline__ void cp_commit() { asm volatile("cp.async.commit_group;\n"); }
__device__ __forceinline__ void cp_wait1()  { asm volatile("cp.async.wait_group 1;\n"); }
__device__ __forceinline__ void cp_wait0()  { asm volatile("cp.async.wait_group 0;\n"); }
__device__ __forceinline__ void prefetchL2(const void* p) {
    asm volatile("prefetch.global.L2 [%0];" :: "l"(p));
}

__device__ __forceinline__ float sigf(float x) { return 1.f / (1.f + __expf(-x)); }
__device__ __forceinline__ float clip3(float v) { return fminf(fmaxf(v, -3.f), 3.f); }
__device__ __forceinline__ void stcs32(__half* p, __half2 v) {
    asm volatile("st.global.cs.b32 [%0], %1;\n" :: "l"(p), "r"(*(uint32_t*)&v));
}

// ------------------------- repack weights + convert x to fp16 -------------------------
__global__ void repack_kernel(const float* __restrict__ x,
                              const float* __restrict__ Wi, const float* __restrict__ Wh,
                              const float* __restrict__ bb, const float* __restrict__ Wp)
{
    size_t stride = (size_t)gridDim.x * blockDim.x;
    size_t tid0 = (size_t)blockIdx.x * blockDim.x + threadIdx.x;
    const size_t NW = 4ull * 16384ull * 512ull;
    for (size_t i = tid0; i < NW; i += stride) {
        size_t ld  = i >> 23;
        size_t rem = i & ((1ull << 23) - 1);
        int np = (int)(rem >> 9), k = (int)(rem & 511);
        int c = np >> 2, g = np & 3;
        size_t src = (ld << 23) + ((size_t)(g * 4096 + c) << 9) + k;
        g_WiH[i] = __float2half_rn(Wi[src]);
        g_WhH[i] = __float2half_rn(Wh[src]);
    }
    for (size_t i = tid0; i < 4ull * 512ull * 4096ull; i += stride)
        g_WpH[i] = __float2half_rn(Wp[i]);
    for (size_t i = tid0; i < 8192ull * 512ull; i += stride)
        g_xH[i] = __float2half_rn(x[i]);
    for (size_t i = tid0; i < 4ull * 16384ull; i += stride) {
        int ld = (int)(i >> 14), np = (int)(i & 16383);
        int c = np >> 2, g = np & 3;
        g_bQ[i] = bb[(ld << 14) + g * 4096 + c];
    }
}

__global__ void zero_state()
{
    int i0 = blockIdx.x * blockDim.x + threadIdx.x, st = gridDim.x * blockDim.x;
    for (int i = i0; i < 2 * 64 * 4096; i += st) g_c[i] = 0.f;
    for (int i = i0; i < 2 * 64 * 512;  i += st) g_hH[i] = __float2half_rn(0.f);
}

// ------------------------- xproj GEMM (fp16, ldmatrix) -------------------------
// C[8192,16384] = A[8192,512] @ WiH^T (+bias). BM=128 BN=128 BK=32(half), 256 thr,
// warps 4(m) x 2(n), warp tile 32x64 -> mma grid 2x8.
__global__ void __launch_bounds__(256) xproj_kernel(int l)
{
    __shared__ __align__(16) uint32_t As[2][128][20];
    __shared__ __align__(16) uint32_t Bs[2][128][20];
    int dir = blockIdx.z;
    int ld = l * 2 + dir;
    const __half* A = (l == 0) ? g_xH : (g_y0H + (size_t)dir * 8192ull * 512ull);
    const __half* Bw = g_WiH + ((size_t)ld << 23);
    int m0 = blockIdx.y * 128, n0 = blockIdx.x * 128;
    int tid = threadIdx.x, lane = tid & 31, w = tid >> 5;
    int wm = w >> 1, wn = w & 1;
    int g = lane >> 2, t4 = lane & 3;
    int lrow = lane & 15, ktop = (lane >> 4) * 4;            // A ldmatrix lane addressing
    int bn = ((lane >> 4) << 3) + (lane & 7);                // B ldmatrix lane addressing
    int bk = ((lane >> 3) & 1) * 4;

    float acc[2][8][4];
#pragma unroll
    for (int a = 0; a < 2; a++)
#pragma unroll
        for (int b = 0; b < 8; b++)
#pragma unroll
            for (int q = 0; q < 4; q++) acc[a][b][q] = 0.f;

    const __half* Ag = A + (size_t)m0 * 512;
    const __half* Bg = Bw + (size_t)n0 * 512;

    auto load = [&](int st, int buf) {
        int k0 = st * 32;
#pragma unroll
        for (int i = 0; i < 2; i++) {
            int idx = tid + 256 * i;
            int r = idx >> 2, q = idx & 3;
            cp16(&As[buf][r][q * 4], Ag + (size_t)r * 512 + k0 + q * 8);
            cp16(&Bs[buf][r][q * 4], Bg + (size_t)r * 512 + k0 + q * 8);
        }
    };

    load(0, 0); cp_commit();
#pragma unroll 1
    for (int st = 0; st < 16; st++) {
        int buf = st & 1;
        if (st + 1 < 16) { load(st + 1, buf ^ 1); cp_commit(); cp_wait1(); }
        else             { cp_wait0(); }
        __syncthreads();
        const uint32_t* Ab = &As[buf][0][0];
        const uint32_t* Bb = &Bs[buf][0][0];
#pragma unroll
        for (int kk = 0; kk < 2; kk++) {
            uint32_t af[2][4], bf[8][2];
#pragma unroll
            for (int mi = 0; mi < 2; mi++)
                ldsm4(af[mi][0], af[mi][1], af[mi][2], af[mi][3],
                      Ab + (wm * 32 + mi * 16 + lrow) * 20 + kk * 8 + ktop);
#pragma unroll
            for (int pr = 0; pr < 4; pr++)
                ldsm4(bf[pr * 2][0], bf[pr * 2][1], bf[pr * 2 + 1][0], bf[pr * 2 + 1][1],
                      Bb + (wn * 64 + pr * 16 + bn) * 20 + kk * 8 + bk);
#pragma unroll
            for (int mi = 0; mi < 2; mi++)
#pragma unroll
                for (int ni = 0; ni < 8; ni++)
                    mmah(acc[mi][ni], af[mi], bf[ni]);
        }
        __syncthreads();
    }

    const float* bias = g_bQ + ld * 16384;
    __half* Co = g_xprojH + (size_t)dir * 8192ull * 16384ull;
#pragma unroll
    for (int mi = 0; mi < 2; mi++) {
        int rm = m0 + wm * 32 + mi * 16 + g;
#pragma unroll
        for (int ni = 0; ni < 8; ni++) {
            int cn = n0 + wn * 64 + ni * 8 + t4 * 2;
            float2 bv = *(const float2*)&bias[cn];
            stcs32(&Co[(size_t)rm * 16384 + cn],
                   __floats2half2_rn(acc[mi][ni][0] + bv.x, acc[mi][ni][1] + bv.y));
            stcs32(&Co[(size_t)(rm + 8) * 16384 + cn],
                   __floats2half2_rn(acc[mi][ni][2] + bv.x, acc[mi][ni][3] + bv.y));
        }
    }
}

// ------------------------- gate step (fp16 GEMM + fused LSTM pointwise) ----------------
// gates[64,128-tile] = h @ WhH^T + xproj[t]; BM=64 BN=128 BK=32(half), 3-stage pipeline,
// 256 thr, warps 2(m) x 4(n), warp tile 32x32 -> mma grid 2x4. ldmatrix fragment loads.
#define GATE_SMEM 46080  // 3*(64*20 + 128*20)*4 ; epilogue gsm 64*132*4 = 33792 fits

__global__ void __launch_bounds__(256) gate_kernel(int l, int s, int last,
                                                   float* __restrict__ out)
{
    extern __shared__ __align__(16) uint32_t smu[];
    uint32_t* Asm = smu;                 // [3][64][20]
    uint32_t* Bsm = smu + 3 * 64 * 20;   // [3][128][20]

    int dir = blockIdx.y;
    int ld = l * 2 + dir;
    int t = dir ? (127 - s) : s;
    int np0 = blockIdx.x * 128;

    const __half* Ag = g_hH + dir * 64 * 512;
    const __half* Bg = g_WhH + ((size_t)ld << 23) + (size_t)np0 * 512;
    const __half* xp = g_xprojH + (size_t)dir * 8192ull * 16384ull;
    uint64_t pol = mk_evict_last();

    int tid = threadIdx.x, lane = tid & 31, w = tid >> 5;
    int wm = w >> 2, wn = w & 3;
    int g = lane >> 2, t4 = lane & 3;
    int lrow = lane & 15, ktop = (lane >> 4) * 4;
    int bn = ((lane >> 4) << 3) + (lane & 7);
    int bk = ((lane >> 3) & 1) * 4;

    // prefetch this step's xproj slice into L2 early
    if (tid < 128) {
        int b = tid >> 1, half128 = tid & 1;
        prefetchL2(xp + (size_t)(b * 128 + t) * 16384 + np0 + half128 * 64);
    }

    float acc[2][4][4];
#pragma unroll
    for (int a = 0; a < 2; a++)
#pragma unroll
        for (int b = 0; b < 4; b++)
#pragma unroll
            for (int q = 0; q < 4; q++) acc[a][b][q] = 0.f;

    auto load = [&](int st, int buf) {
        int k0 = st * 32;
        {
            int r = tid >> 2, q = tid & 3;
            cp16(&Asm[(buf * 64 + r) * 20 + q * 4], Ag + (size_t)r * 512 + k0 + q * 8);
        }
#pragma unroll
        for (int i = 0; i < 2; i++) {
            int idx = tid + 256 * i;
            int r = idx >> 2, q = idx & 3;
            cp16_el(&Bsm[(buf * 128 + r) * 20 + q * 4],
                    Bg + (size_t)r * 512 + k0 + q * 8, pol);
        }
    };

    load(0, 0); cp_commit();
    load(1, 1); cp_commit();
#pragma unroll 1
    for (int st = 0; st < 16; st++) {
        if (st < 15) cp_wait1(); else cp_wait0();
        __syncthreads();
        if (st + 2 < 16) { load(st + 2, (st + 2) % 3); cp_commit(); }
        int buf = st % 3;
        const uint32_t* Ab = Asm + buf * 64 * 20;
        const uint32_t* Bb = Bsm + buf * 128 * 20;
#pragma unroll
        for (int kk = 0; kk < 2; kk++) {
            uint32_t af[2][4], bf[4][2];
#pragma unroll
            for (int mi = 0; mi < 2; mi++)
                ldsm4(af[mi][0], af[mi][1], af[mi][2], af[mi][3],
                      Ab + (wm * 32 + mi * 16 + lrow) * 20 + kk * 8 + ktop);
#pragma unroll
            for (int pr = 0; pr < 2; pr++)
                ldsm4(bf[pr * 2][0], bf[pr * 2][1], bf[pr * 2 + 1][0], bf[pr * 2 + 1][1],
                      Bb + (wn * 32 + pr * 16 + bn) * 20 + kk * 8 + bk);
#pragma unroll
            for (int mi = 0; mi < 2; mi++)
#pragma unroll
                for (int ni = 0; ni < 4; ni++)
                    mmah(acc[mi][ni], af[mi], bf[ni]);
        }
    }
    __syncthreads();

    float* gsm = (float*)smu;            // [64][132]
#pragma unroll
    for (int mi = 0; mi < 2; mi++) {
        int r = wm * 32 + mi * 16 + g;
#pragma unroll
        for (int ni = 0; ni < 4; ni++) {
            int n = wn * 32 + ni * 8 + t4 * 2;
            gsm[r * 132 + n]           = acc[mi][ni][0];
            gsm[r * 132 + n + 1]       = acc[mi][ni][1];
            gsm[(r + 8) * 132 + n]     = acc[mi][ni][2];
            gsm[(r + 8) * 132 + n + 1] = acc[mi][ni][3];
        }
    }
    __syncthreads();

#pragma unroll 1
    for (int p = 0; p < 4; p++) {
        int idx = p * 256 + tid;
        int q2 = idx & 15, b = idx >> 4;
        const uint4* xr = (const uint4*)(xp + (size_t)(b * 128 + t) * 16384 + np0 + q2 * 8);
        uint4 xv = __ldcs(xr);
        float2 x0 = __half22float2(*(__half2*)&xv.x);
        float2 x1 = __half22float2(*(__half2*)&xv.y);
        float2 x2 = __half22float2(*(__half2*)&xv.z);
        float2 x3 = __half22float2(*(__half2*)&xv.w);
        float4 gA = *(const float4*)&gsm[b * 132 + q2 * 8];
        float4 gB = *(const float4*)&gsm[b * 132 + q2 * 8 + 4];

        int cg0 = (np0 >> 2) + q2 * 2;
        int ci0 = dir * 64 * 4096 + b * 4096 + cg0;
        {
            float ii = sigf(gA.x + x0.x), ff = sigf(gA.y + x0.y);
            float gg = tanhf(gA.z + x1.x), oo = sigf(gA.w + x1.y);
            float cn = clip3(ii * gg + ff * g_c[ci0]);
            g_c[ci0] = cn;
            g_aH[ci0] = __float2half_rn(oo * tanhf(cn));
            if (last)
                out[CS_OFF + (size_t)(l * 64 + b) * 8192 + dir * 4096 + cg0] = cn;
        }
        {
            float ii = sigf(gB.x + x2.x), ff = sigf(gB.y + x2.y);
            float gg = tanhf(gB.z + x3.x), oo = sigf(gB.w + x3.y);
            float cn = clip3(ii * gg + ff * g_c[ci0 + 1]);
            g_c[ci0 + 1] = cn;
            g_aH[ci0 + 1] = __float2half_rn(oo * tanhf(cn));
            if (last)
                out[CS_OFF + (size_t)(l * 64 + b) * 8192 + dir * 4096 + cg0 + 1] = cn;
        }
    }
}

// ------------------------- output-stationary projection (no split-K, no reduce) --------
// grid (16 ntiles, 2 mtiles, 2 dirs) = 64 CTAs. Each computes h[32,32] with full K=4096,
// then directly writes clipped h (fp16 state) + seq/HS outputs. BK=64, 3-stage pipeline.
__global__ void __launch_bounds__(256) projd_kernel(int l, int s, int last,
                                                    float* __restrict__ out)
{
    __shared__ __align__(16) uint32_t As[3][32][36];
    __shared__ __align__(16) uint32_t Bs[3][32][36];
    int ntile = blockIdx.x;       // 0..15 -> 32 cols each
    int mtile = blockIdx.y;       // 0..1  -> 32 rows each
    int dir = blockIdx.z, ld = l * 2 + dir;
    int n0 = ntile * 32, m0 = mtile * 32;

    const __half* Ag = g_aH + dir * 64 * 4096 + (size_t)m0 * 4096;
    const __half* Bg = g_WpH + (size_t)ld * 512 * 4096 + (size_t)n0 * 4096;
    uint64_t pol = mk_evict_last();

    int tid = threadIdx.x, lane = tid & 31, w = tid >> 5;
    int wm = w >> 2, wn = w & 3;                   // 2(m) x 4(n) warps
    int g = lane >> 2, t4 = lane & 3;
    int lrow = lane & 15, ktop = (lane >> 4) * 4;  // A ldmatrix lanes
    int l16 = lane & 15;
    int brow = l16 & 7, bk = ((l16 >> 3) & 1) * 4; // B ldmatrix (x2) lanes

    float acc[4] = {0.f, 0.f, 0.f, 0.f};

    auto load = [&](int st, int buf) {
        int k0 = st * 64;
        int r = tid >> 3, q = tid & 7;             // 32 rows x 8 quads
        cp16(&As[buf][r][q * 4], Ag + (size_t)r * 4096 + k0 + q * 8);
        cp16_el(&Bs[buf][r][q * 4], Bg + (size_t)r * 4096 + k0 + q * 8, pol);
    };

    load(0, 0); cp_commit();
    load(1, 1); cp_commit();
#pragma unroll 1
    for (int st = 0; st < 64; st++) {
        if (st < 63) cp_wait1(); else cp_wait0();
        __syncthreads();
        if (st + 2 < 64) { load(st + 2, (st + 2) % 3); cp_commit(); }
        int buf = st % 3;
        const uint32_t* Ab = &As[buf][0][0];
        const uint32_t* Bb = &Bs[buf][0][0];
#pragma unroll
        for (int kk = 0; kk < 4; kk++) {
            uint32_t af[4], bf[2];
            ldsm4(af[0], af[1], af[2], af[3],
                  Ab + (wm * 16 + lrow) * 36 + kk * 8 + ktop);
            ldsm2(bf[0], bf[1],
                  Bb + (wn * 8 + brow) * 36 + kk * 8 + bk);
            mmah(acc, af, bf);
        }
        __syncthreads();
    }

    // epilogue: clip -> h state + outputs (2 rows x 2 cols per thread)
    int t = dir ? (127 - s) : s;
    int j = n0 + wn * 8 + t4 * 2;
#pragma unroll
    for (int rr = 0; rr < 2; rr++) {
        int b = m0 + wm * 16 + g + rr * 8;
        float h0 = clip3(acc[rr * 2]), h1 = clip3(acc[rr * 2 + 1]);

        *(__half2*)&g_hH[dir * 32768 + b * 512 + j] = __floats2half2_rn(h0, h1);

        size_t yi = (size_t)(b * 128 + t) * 512 + j;
        __half2* yp = (__half2*)&g_y0H[(size_t)dir * 8192ull * 512ull + yi];
        float2 yv = make_float2(h0, h1);
        if (l == 0) {
            *yp = __floats2half2_rn(h0, h1);
        } else {
            float2 a0 = __half22float2(*yp);
            yv.x += a0.x; yv.y += a0.y;
        }
        *(float2*)&out[SEQ_OFF + ((size_t)(l * 64 + b) * 128 + t) * 1024 + dir * 512 + j] = yv;
        if (last)
            *(float2*)&out[HS_OFF + (size_t)(l * 64 + b) * 1024 + dir * 512 + j] =
                make_float2(h0, h1);
    }
}

// ------------------------- launch (single stream, 2 kernels per step) -------------------
extern "C" void kernel_launch(void* const* d_in, const int* in_sizes, int n_in,
                              void* d_out, int out_size)
{
    const float* x  = (const float*)d_in[0];
    const float* Wi = (const float*)d_in[1];
    const float* Wh = (const float*)d_in[2];
    const float* bb = (const float*)d_in[3];
    const float* Wp = (const float*)d_in[4];
    float* out = (float*)d_out;

    cudaFuncSetAttribute(gate_kernel,
                         cudaFuncAttributeMaxDynamicSharedMemorySize, GATE_SMEM);

    repack_kernel<<<2048, 256>>>(x, Wi, Wh, bb, Wp);

    for (int l = 0; l < 2; l++) {
        zero_state<<<512, 256>>>();
        xproj_kernel<<<dim3(128, 64, 2), 256>>>(l);
        for (int s = 0; s < 128; s++) {
            int last = (s == 127) ? 1 : 0;
            gate_kernel<<<dim3(128, 2), 256, GATE_SMEM>>>(l, s, last, out);
            projd_kernel<<<dim3(16, 2, 2), 256>>>(l, s, last, out);
        }
    }
}

// round 14
// speedup vs baseline: 1.3757x; 1.3757x over previous
#include <cuda_runtime.h>
#include <cuda_fp16.h>
#include <cstdint>
#include <cstddef>

// Shapes: B=64, T=128, D=512, H=512, C=4096, 4C=16384, L=2, DIRS=2
// d_out packing (float32): seq [2,64,128,1024] | hs [2,64,1024] | cs [2,64,8192]
#define SEQ_OFF   0ull
#define HS_OFF    16777216ull
#define CS_OFF    16908288ull

// ------------------------- device scratch -------------------------
__device__ __align__(16) __half g_xprojH[2ull*8192ull*16384ull]; // l0 xproj [dir][b*128+t][np]
__device__ __align__(16) __half g_Wi0H[2ull*16384ull*512ull];    // l0 Wi [dir][np][k]
__device__ __align__(16) __half g_Wh0H[2ull*16384ull*512ull];    // l0 Wh [dir][np][k]
__device__ __align__(16) __half g_Wc1H[2ull*16384ull*1024ull];   // l1 [Wh1|Wi1] [dir][np][k2]
__device__ __align__(16) __half g_WpH[4ull*512ull*4096ull];      // [ld][h][c]
__device__ __align__(16) __half g_xH[8192ull*512ull];            // x as fp16
__device__ __align__(16) __half g_y0H[2ull*8192ull*512ull];      // layer-0 outputs (fp16)
__device__ __align__(16) __half g_aH[4*64*4096];                 // o*tanh(c) per (l,dir)
__device__ __align__(16) __half g_hH[4*64*512];                  // hidden state per (l,dir)
__device__ float g_c[4*64*4096];                                 // cell state fp32
__device__ float g_part[4*16*64*512];                            // proj partials per (l,dir)
__device__ float g_bQ[4*16384];                                  // interleaved bias fp32

// ------------------------- helpers -------------------------
__device__ __forceinline__ void mmah(float* c, const uint32_t* a, const uint32_t* b) {
    asm volatile(
        "mma.sync.aligned.m16n8k16.row.col.f32.f16.f16.f32 "
        "{%0,%1,%2,%3}, {%4,%5,%6,%7}, {%8,%9}, {%0,%1,%2,%3};\n"
        : "+f"(c[0]), "+f"(c[1]), "+f"(c[2]), "+f"(c[3])
        : "r"(a[0]), "r"(a[1]), "r"(a[2]), "r"(a[3]), "r"(b[0]), "r"(b[1]));
}
__device__ __forceinline__ void ldsm4(uint32_t& r0, uint32_t& r1, uint32_t& r2, uint32_t& r3,
                                      const uint32_t* p) {
    uint32_t a = (uint32_t)__cvta_generic_to_shared(p);
    asm volatile("ldmatrix.sync.aligned.m8n8.x4.shared.b16 {%0,%1,%2,%3}, [%4];"
                 : "=r"(r0), "=r"(r1), "=r"(r2), "=r"(r3) : "r"(a));
}
__device__ __forceinline__ void cp16(void* smem, const void* g) {
    uint32_t s = (uint32_t)__cvta_generic_to_shared(smem);
    asm volatile("cp.async.cg.shared.global [%0], [%1], 16;\n" :: "r"(s), "l"(g));
}
__device__ __forceinline__ uint64_t mk_evict_last() {
    uint64_t p;
    asm("createpolicy.fractional.L2::evict_last.b64 %0, 1.0;" : "=l"(p));
    return p;
}
__device__ __forceinline__ void cp16_el(void* smem, const void* g, uint64_t pol) {
    uint32_t s = (uint32_t)__cvta_generic_to_shared(smem);
    asm volatile("cp.async.cg.shared.global.L2::cache_hint [%0], [%1], 16, %2;\n"
                 :: "r"(s), "l"(g), "l"(pol));
}
__device__ __forceinline__ void cp_commit() { asm volatile("cp.async.commit_group;\n"); }
__device__ __forceinline__ void cp_wait1()  { asm volatile("cp.async.wait_group 1;\n"); }
__device__ __forceinline__ void cp_wait0()  { asm volatile("cp.async.wait_group 0;\n"); }
__device__ __forceinline__ void prefetchL2(const void* p) {
    asm volatile("prefetch.global.L2 [%0];" :: "l"(p));
}

__device__ __forceinline__ float sigf(float x) { return 1.f / (1.f + __expf(-x)); }
__device__ __forceinline__ float clip3(float v) { return fminf(fmaxf(v, -3.f), 3.f); }
__device__ __forceinline__ void stcs32(__half* p, __half2 v) {
    asm volatile("st.global.cs.b32 [%0], %1;\n" :: "l"(p), "r"(*(uint32_t*)&v));
}

// ------------------------- repack weights + convert x to fp16 -------------------------
__global__ void repack_kernel(const float* __restrict__ x,
                              const float* __restrict__ Wi, const float* __restrict__ Wh,
                              const float* __restrict__ bb, const float* __restrict__ Wp)
{
    size_t stride = (size_t)gridDim.x * blockDim.x;
    size_t tid0 = (size_t)blockIdx.x * blockDim.x + threadIdx.x;

    // layer 0: Wi0 / Wh0, interleaved np = c*4+g, K=512
    const size_t N1 = 2ull * 16384ull * 512ull;
    for (size_t i = tid0; i < N1; i += stride) {
        size_t dir = i >> 23;
        size_t rem = i & ((1ull << 23) - 1);
        int np = (int)(rem >> 9), k = (int)(rem & 511);
        int c = np >> 2, g = np & 3;
        size_t src = (dir << 23) + ((size_t)(g * 4096 + c) << 9) + k;   // ld = dir (layer 0)
        g_Wi0H[i] = __float2half_rn(Wi[src]);
        g_Wh0H[i] = __float2half_rn(Wh[src]);
    }
    // layer 1: Wc1 = [Wh1 | Wi1], K=1024
    const size_t N2 = 2ull * 16384ull * 1024ull;
    for (size_t i = tid0; i < N2; i += stride) {
        size_t dir = i >> 24;
        size_t rem = i & ((1ull << 24) - 1);
        int np = (int)(rem >> 10), k = (int)(rem & 1023);
        int c = np >> 2, g = np & 3;
        size_t ld = 2 + dir;
        if (k < 512) {
            size_t src = (ld << 23) + ((size_t)(g * 4096 + c) << 9) + k;
            g_Wc1H[i] = __float2half_rn(Wh[src]);
        } else {
            size_t src = (ld << 23) + ((size_t)(g * 4096 + c) << 9) + (k - 512);
            g_Wc1H[i] = __float2half_rn(Wi[src]);
        }
    }
    for (size_t i = tid0; i < 4ull * 512ull * 4096ull; i += stride)
        g_WpH[i] = __float2half_rn(Wp[i]);
    for (size_t i = tid0; i < 8192ull * 512ull; i += stride)
        g_xH[i] = __float2half_rn(x[i]);
    for (size_t i = tid0; i < 4ull * 16384ull; i += stride) {
        int ld = (int)(i >> 14), np = (int)(i & 16383);
        int c = np >> 2, g = np & 3;
        g_bQ[i] = bb[(ld << 14) + g * 4096 + c];
    }
}

__global__ void zero_state()
{
    int i0 = blockIdx.x * blockDim.x + threadIdx.x, st = gridDim.x * blockDim.x;
    for (int i = i0; i < 4 * 64 * 4096; i += st) g_c[i] = 0.f;
    for (int i = i0; i < 4 * 64 * 512;  i += st) g_hH[i] = __float2half_rn(0.f);
}

// ------------------------- xproj GEMM for layer 0 only -------------------------
// C[8192,16384] = x[8192,512] @ Wi0^T (+bias). BM=128 BN=128 BK=32(half), 256 thr.
__global__ void __launch_bounds__(256) xproj_kernel()
{
    __shared__ __align__(16) uint32_t As[2][128][20];
    __shared__ __align__(16) uint32_t Bs[2][128][20];
    int dir = blockIdx.z;
    const __half* Bw = g_Wi0H + ((size_t)dir << 23);
    int m0 = blockIdx.y * 128, n0 = blockIdx.x * 128;
    int tid = threadIdx.x, lane = tid & 31, w = tid >> 5;
    int wm = w >> 1, wn = w & 1;
    int g = lane >> 2, t4 = lane & 3;
    int lrow = lane & 15, ktop = (lane >> 4) * 4;
    int bn = ((lane >> 4) << 3) + (lane & 7);
    int bk = ((lane >> 3) & 1) * 4;

    float acc[2][8][4];
#pragma unroll
    for (int a = 0; a < 2; a++)
#pragma unroll
        for (int b = 0; b < 8; b++)
#pragma unroll
            for (int q = 0; q < 4; q++) acc[a][b][q] = 0.f;

    const __half* Ag = g_xH + (size_t)m0 * 512;
    const __half* Bg = Bw + (size_t)n0 * 512;

    auto load = [&](int st, int buf) {
        int k0 = st * 32;
#pragma unroll
        for (int i = 0; i < 2; i++) {
            int idx = tid + 256 * i;
            int r = idx >> 2, q = idx & 3;
            cp16(&As[buf][r][q * 4], Ag + (size_t)r * 512 + k0 + q * 8);
            cp16(&Bs[buf][r][q * 4], Bg + (size_t)r * 512 + k0 + q * 8);
        }
    };

    load(0, 0); cp_commit();
#pragma unroll 1
    for (int st = 0; st < 16; st++) {
        int buf = st & 1;
        if (st + 1 < 16) { load(st + 1, buf ^ 1); cp_commit(); cp_wait1(); }
        else             { cp_wait0(); }
        __syncthreads();
        const uint32_t* Ab = &As[buf][0][0];
        const uint32_t* Bb = &Bs[buf][0][0];
#pragma unroll
        for (int kk = 0; kk < 2; kk++) {
            uint32_t af[2][4], bf[8][2];
#pragma unroll
            for (int mi = 0; mi < 2; mi++)
                ldsm4(af[mi][0], af[mi][1], af[mi][2], af[mi][3],
                      Ab + (wm * 32 + mi * 16 + lrow) * 20 + kk * 8 + ktop);
#pragma unroll
            for (int pr = 0; pr < 4; pr++)
                ldsm4(bf[pr * 2][0], bf[pr * 2][1], bf[pr * 2 + 1][0], bf[pr * 2 + 1][1],
                      Bb + (wn * 64 + pr * 16 + bn) * 20 + kk * 8 + bk);
#pragma unroll
            for (int mi = 0; mi < 2; mi++)
#pragma unroll
                for (int ni = 0; ni < 8; ni++)
                    mmah(acc[mi][ni], af[mi], bf[ni]);
        }
        __syncthreads();
    }

    const float* bias = g_bQ + dir * 16384;
    __half* Co = g_xprojH + (size_t)dir * 8192ull * 16384ull;
#pragma unroll
    for (int mi = 0; mi < 2; mi++) {
        int rm = m0 + wm * 32 + mi * 16 + g;
#pragma unroll
        for (int ni = 0; ni < 8; ni++) {
            int cn = n0 + wn * 64 + ni * 8 + t4 * 2;
            float2 bv = *(const float2*)&bias[cn];
            stcs32(&Co[(size_t)rm * 16384 + cn],
                   __floats2half2_rn(acc[mi][ni][0] + bv.x, acc[mi][ni][1] + bv.y));
            stcs32(&Co[(size_t)(rm + 8) * 16384 + cn],
                   __floats2half2_rn(acc[mi][ni][2] + bv.x, acc[mi][ni][3] + bv.y));
        }
    }
}

// ------------------------- gate slot kernel (both layers pipelined) --------------------
// blockIdx.y = ld (l=ld>>1, dir=ld&1). l0: step=slot, K=512, epi adds xproj slice.
// l1: step=slot-1, K=1024 with A=[h1, y0[t]], epi adds bias. BM=64 BN=128 BK=32, 3-stage.
#define GATE_SMEM 46080

__global__ void __launch_bounds__(256) gate_kernel(int slot, float* __restrict__ out)
{
    extern __shared__ __align__(16) uint32_t smu[];
    uint32_t* Asm = smu;                 // [3][64][20]
    uint32_t* Bsm = smu + 3 * 64 * 20;   // [3][128][20]

    int ld = blockIdx.y;
    int l = ld >> 1, dir = ld & 1;
    int step = (l == 0) ? slot : slot - 1;
    if (step < 0 || step > 127) return;
    int last = (step == 127) ? 1 : 0;
    int t = dir ? (127 - step) : step;
    int np0 = blockIdx.x * 128;
    int KS = (l == 0) ? 16 : 32;         // BK=32-half stages

    const __half* hA = g_hH + ld * 64 * 512;
    const __half* inA = g_y0H + (size_t)dir * 8192ull * 512ull;   // l1 only
    const __half* Bg = (l == 0)
        ? (g_Wh0H + ((size_t)dir << 23) + (size_t)np0 * 512)
        : (g_Wc1H + ((size_t)dir << 24) + (size_t)np0 * 1024);
    size_t wstride = (l == 0) ? 512 : 1024;
    const __half* xp = g_xprojH + (size_t)dir * 8192ull * 16384ull;
    uint64_t pol = mk_evict_last();

    int tid = threadIdx.x, lane = tid & 31, w = tid >> 5;
    int wm = w >> 2, wn = w & 3;
    int g = lane >> 2, t4 = lane & 3;
    int lrow = lane & 15, ktop = (lane >> 4) * 4;
    int bn = ((lane >> 4) << 3) + (lane & 7);
    int bk = ((lane >> 3) & 1) * 4;

    // prefetch epilogue/input data into L2 early
    if (l == 0) {
        if (tid < 128) {
            int b = tid >> 1, half128 = tid & 1;
            prefetchL2(xp + (size_t)(b * 128 + t) * 16384 + np0 + half128 * 64);
        }
    } else {
        int r = tid >> 2, seg = tid & 3;
        prefetchL2(inA + (size_t)(r * 128 + t) * 512 + seg * 128);
    }

    float acc[2][4][4];
#pragma unroll
    for (int a = 0; a < 2; a++)
#pragma unroll
        for (int b = 0; b < 4; b++)
#pragma unroll
            for (int q = 0; q < 4; q++) acc[a][b][q] = 0.f;

    auto load = [&](int st, int buf) {
        int k0 = st * 32;
        {
            int r = tid >> 2, q = tid & 3;
            const __half* src;
            if (k0 < 512) src = hA + (size_t)r * 512 + k0 + q * 8;
            else          src = inA + (size_t)(r * 128 + t) * 512 + (k0 - 512) + q * 8;
            cp16(&Asm[(buf * 64 + r) * 20 + q * 4], src);
        }
#pragma unroll
        for (int i = 0; i < 2; i++) {
            int idx = tid + 256 * i;
            int r = idx >> 2, q = idx & 3;
            cp16_el(&Bsm[(buf * 128 + r) * 20 + q * 4],
                    Bg + (size_t)r * wstride + k0 + q * 8, pol);
        }
    };

    load(0, 0); cp_commit();
    load(1, 1); cp_commit();
#pragma unroll 1
    for (int st = 0; st < KS; st++) {
        if (st < KS - 1) cp_wait1(); else cp_wait0();
        __syncthreads();
        if (st + 2 < KS) { load(st + 2, (st + 2) % 3); cp_commit(); }
        int buf = st % 3;
        const uint32_t* Ab = Asm + buf * 64 * 20;
        const uint32_t* Bb = Bsm + buf * 128 * 20;
#pragma unroll
        for (int kk = 0; kk < 2; kk++) {
            uint32_t af[2][4], bf[4][2];
#pragma unroll
            for (int mi = 0; mi < 2; mi++)
                ldsm4(af[mi][0], af[mi][1], af[mi][2], af[mi][3],
                      Ab + (wm * 32 + mi * 16 + lrow) * 20 + kk * 8 + ktop);
#pragma unroll
            for (int pr = 0; pr < 2; pr++)
                ldsm4(bf[pr * 2][0], bf[pr * 2][1], bf[pr * 2 + 1][0], bf[pr * 2 + 1][1],
                      Bb + (wn * 32 + pr * 16 + bn) * 20 + kk * 8 + bk);
#pragma unroll
            for (int mi = 0; mi < 2; mi++)
#pragma unroll
                for (int ni = 0; ni < 4; ni++)
                    mmah(acc[mi][ni], af[mi], bf[ni]);
        }
    }
    __syncthreads();

    float* gsm = (float*)smu;            // [64][132]
#pragma unroll
    for (int mi = 0; mi < 2; mi++) {
        int r = wm * 32 + mi * 16 + g;
#pragma unroll
        for (int ni = 0; ni < 4; ni++) {
            int n = wn * 32 + ni * 8 + t4 * 2;
            gsm[r * 132 + n]           = acc[mi][ni][0];
            gsm[r * 132 + n + 1]       = acc[mi][ni][1];
            gsm[(r + 8) * 132 + n]     = acc[mi][ni][2];
            gsm[(r + 8) * 132 + n + 1] = acc[mi][ni][3];
        }
    }
    __syncthreads();

    const float* bq = g_bQ + ld * 16384;
#pragma unroll 1
    for (int p = 0; p < 4; p++) {
        int idx = p * 256 + tid;
        int q2 = idx & 15, b = idx >> 4;
        float2 x0, x1, x2, x3;
        if (l == 0) {
            const uint4* xr = (const uint4*)(xp + (size_t)(b * 128 + t) * 16384 + np0 + q2 * 8);
            uint4 xv = __ldcs(xr);
            x0 = __half22float2(*(__half2*)&xv.x);
            x1 = __half22float2(*(__half2*)&xv.y);
            x2 = __half22float2(*(__half2*)&xv.z);
            x3 = __half22float2(*(__half2*)&xv.w);
        } else {
            float4 bv0 = *(const float4*)&bq[np0 + q2 * 8];
            float4 bv1 = *(const float4*)&bq[np0 + q2 * 8 + 4];
            x0 = make_float2(bv0.x, bv0.y);
            x1 = make_float2(bv0.z, bv0.w);
            x2 = make_float2(bv1.x, bv1.y);
            x3 = make_float2(bv1.z, bv1.w);
        }
        float4 gA = *(const float4*)&gsm[b * 132 + q2 * 8];
        float4 gB = *(const float4*)&gsm[b * 132 + q2 * 8 + 4];

        int cg0 = (np0 >> 2) + q2 * 2;
        int ci0 = ld * 64 * 4096 + b * 4096 + cg0;
        {
            float ii = sigf(gA.x + x0.x), ff = sigf(gA.y + x0.y);
            float gg = tanhf(gA.z + x1.x), oo = sigf(gA.w + x1.y);
            float cn = clip3(ii * gg + ff * g_c[ci0]);
            g_c[ci0] = cn;
            g_aH[ci0] = __float2half_rn(oo * tanhf(cn));
            if (last)
                out[CS_OFF + (size_t)(l * 64 + b) * 8192 + dir * 4096 + cg0] = cn;
        }
        {
            float ii = sigf(gB.x + x2.x), ff = sigf(gB.y + x2.y);
            float gg = tanhf(gB.z + x3.x), oo = sigf(gB.w + x3.y);
            float cn = clip3(ii * gg + ff * g_c[ci0 + 1]);
            g_c[ci0 + 1] = cn;
            g_aH[ci0 + 1] = __float2half_rn(oo * tanhf(cn));
            if (last)
                out[CS_OFF + (size_t)(l * 64 + b) * 8192 + dir * 4096 + cg0 + 1] = cn;
        }
    }
}

// ------------------------- projection GEMM (split-K) both layers -----------------------
// grid (4 n0, 16 kk, 4 ld). part[ld][kk][64,512] = a[ld][64, kslice] @ Wp[ld]^T
__global__ void __launch_bounds__(256) proj_kernel(int slot)
{
    __shared__ __align__(16) uint32_t As[2][64][20];
    __shared__ __align__(16) uint32_t Bs[2][128][20];
    int ld = blockIdx.z;
    int l = ld >> 1;
    int step = (l == 0) ? slot : slot - 1;
    if (step < 0 || step > 127) return;
    int n0 = blockIdx.x * 128;
    int kk = blockIdx.y;
    int kc0 = kk * 256;

    const __half* Ag = g_aH + ld * 64 * 4096 + kc0;
    const __half* Bg = g_WpH + (size_t)ld * 512 * 4096 + (size_t)n0 * 4096 + kc0;
    uint64_t pol = mk_evict_last();

    int tid = threadIdx.x, lane = tid & 31, w = tid >> 5;
    int wm = w >> 2, wn = w & 3;
    int g = lane >> 2, t4 = lane & 3;
    int lrow = lane & 15, ktop = (lane >> 4) * 4;
    int bn = ((lane >> 4) << 3) + (lane & 7);
    int bk = ((lane >> 3) & 1) * 4;

    float acc[2][4][4];
#pragma unroll
    for (int a = 0; a < 2; a++)
#pragma unroll
        for (int b = 0; b < 4; b++)
#pragma unroll
            for (int q = 0; q < 4; q++) acc[a][b][q] = 0.f;

    auto load = [&](int st, int buf) {
        int k0 = st * 32;
        {
            int r = tid >> 2, q = tid & 3;
            cp16(&As[buf][r][q * 4], Ag + (size_t)r * 4096 + k0 + q * 8);
        }
#pragma unroll
        for (int i = 0; i < 2; i++) {
            int idx = tid + 256 * i;
            int r = idx >> 2, q = idx & 3;
            cp16_el(&Bs[buf][r][q * 4], Bg + (size_t)r * 4096 + k0 + q * 8, pol);
        }
    };

    load(0, 0); cp_commit();
#pragma unroll 1
    for (int st = 0; st < 8; st++) {
        int buf = st & 1;
        if (st + 1 < 8) { load(st + 1, buf ^ 1); cp_commit(); cp_wait1(); }
        else            { cp_wait0(); }
        __syncthreads();
        const uint32_t* Ab = &As[buf][0][0];
        const uint32_t* Bb = &Bs[buf][0][0];
#pragma unroll
        for (int kk2 = 0; kk2 < 2; kk2++) {
            uint32_t af[2][4], bf[4][2];
#pragma unroll
            for (int mi = 0; mi < 2; mi++)
                ldsm4(af[mi][0], af[mi][1], af[mi][2], af[mi][3],
                      Ab + (wm * 32 + mi * 16 + lrow) * 20 + kk2 * 8 + ktop);
#pragma unroll
            for (int pr = 0; pr < 2; pr++)
                ldsm4(bf[pr * 2][0], bf[pr * 2][1], bf[pr * 2 + 1][0], bf[pr * 2 + 1][1],
                      Bb + (wn * 32 + pr * 16 + bn) * 20 + kk2 * 8 + bk);
#pragma unroll
            for (int mi = 0; mi < 2; mi++)
#pragma unroll
                for (int ni = 0; ni < 4; ni++)
                    mmah(acc[mi][ni], af[mi], bf[ni]);
        }
        __syncthreads();
    }

    float* P = g_part + ((size_t)(ld * 16 + kk) * 64) * 512;
#pragma unroll
    for (int mi = 0; mi < 2; mi++) {
        int rm = wm * 32 + mi * 16 + g;
#pragma unroll
        for (int ni = 0; ni < 4; ni++) {
            int cn = n0 + wn * 32 + ni * 8 + t4 * 2;
            *(float2*)&P[(size_t)rm * 512 + cn] =
                make_float2(acc[mi][ni][0], acc[mi][ni][1]);
            *(float2*)&P[(size_t)(rm + 8) * 512 + cn] =
                make_float2(acc[mi][ni][2], acc[mi][ni][3]);
        }
    }
}

// ------------------------- reduce + clip + outputs (both layers) -----------------------
__global__ void reduce_kernel(int slot, float* __restrict__ out)
{
    int e = blockIdx.x * 256 + threadIdx.x;     // 131072 elements
    int ld = e >> 15;
    int l = ld >> 1, dir = ld & 1;
    int step = (l == 0) ? slot : slot - 1;
    if (step < 0 || step > 127) return;
    int last = (step == 127) ? 1 : 0;
    int r = e & 32767;
    int b = r >> 9, j = r & 511;
    int t = dir ? (127 - step) : step;

    const float* p = g_part + (size_t)ld * 16 * 64 * 512 + b * 512 + j;
    float sum = 0.f;
#pragma unroll
    for (int k = 0; k < 16; k++) sum += __ldcg(&p[(size_t)k * 64 * 512]);
    float h = clip3(sum);

    g_hH[ld * 32768 + b * 512 + j] = __float2half_rn(h);

    size_t yi = (size_t)(b * 128 + t) * 512 + j;
    float yv = h;
    if (l == 0) g_y0H[(size_t)dir * 8192ull * 512ull + yi] = __float2half_rn(h);
    else        yv = h + __half2float(g_y0H[(size_t)dir * 8192ull * 512ull + yi]);

    __stcs(&out[SEQ_OFF + ((size_t)(l * 64 + b) * 128 + t) * 1024 + dir * 512 + j], yv);
    if (last)
        __stcs(&out[HS_OFF + (size_t)(l * 64 + b) * 1024 + dir * 512 + j], h);
}

// ------------------------- launch: layer-pipelined slots -------------------------
extern "C" void kernel_launch(void* const* d_in, const int* in_sizes, int n_in,
                              void* d_out, int out_size)
{
    const float* x  = (const float*)d_in[0];
    const float* Wi = (const float*)d_in[1];
    const float* Wh = (const float*)d_in[2];
    const float* bb = (const float*)d_in[3];
    const float* Wp = (const float*)d_in[4];
    float* out = (float*)d_out;

    cudaFuncSetAttribute(gate_kernel,
                         cudaFuncAttributeMaxDynamicSharedMemorySize, GATE_SMEM);

    repack_kernel<<<2048, 256>>>(x, Wi, Wh, bb, Wp);
    zero_state<<<512, 256>>>();
    xproj_kernel<<<dim3(128, 64, 2), 256>>>();

    for (int slot = 0; slot <= 128; slot++) {
        gate_kernel<<<dim3(128, 4), 256, GATE_SMEM>>>(slot, out);
        proj_kernel<<<dim3(4, 16, 4), 256>>>(slot);
        reduce_kernel<<<512, 256>>>(slot, out);
    }
}

// round 15
// speedup vs baseline: 1.4290x; 1.0387x over previous
#include <cuda_runtime.h>
#include <cuda_fp16.h>
#include <cstdint>
#include <cstddef>

// Shapes: B=64, T=128, D=512, H=512, C=4096, 4C=16384, L=2, DIRS=2
// d_out packing (float32): seq [2,64,128,1024] | hs [2,64,1024] | cs [2,64,8192]
#define SEQ_OFF   0ull
#define HS_OFF    16777216ull
#define CS_OFF    16908288ull

// ------------------------- device scratch -------------------------
__device__ __align__(16) __half g_xprojH[2ull*8192ull*16384ull]; // l0 xproj [dir][b*128+t][np]
__device__ __align__(16) __half g_Wi0H[2ull*16384ull*512ull];    // l0 Wi [dir][np][k]
__device__ __align__(16) __half g_Wh0H[2ull*16384ull*512ull];    // l0 Wh [dir][np][k]
__device__ __align__(16) __half g_Wc1H[2ull*16384ull*1024ull];   // l1 [Wh1|Wi1] [dir][np][k2]
__device__ __align__(16) __half g_WpH[4ull*512ull*4096ull];      // [ld][h][c]
__device__ __align__(16) __half g_xH[8192ull*512ull];            // x as fp16
__device__ __align__(16) __half g_y0H[2ull*8192ull*512ull];      // layer-0 outputs (fp16)
__device__ __align__(16) __half g_aH[4*64*4096];                 // o*tanh(c) per (l,dir)
__device__ __align__(16) __half g_hH[4*64*512];                  // hidden state per (l,dir)
__device__ float g_c[4*64*4096];                                 // cell state fp32
__device__ float g_part[4*16*64*512];                            // proj partials per (l,dir)
__device__ float g_bQ[4*16384];                                  // interleaved bias fp32

// ------------------------- helpers -------------------------
__device__ __forceinline__ void mmah(float* c, const uint32_t* a, const uint32_t* b) {
    asm volatile(
        "mma.sync.aligned.m16n8k16.row.col.f32.f16.f16.f32 "
        "{%0,%1,%2,%3}, {%4,%5,%6,%7}, {%8,%9}, {%0,%1,%2,%3};\n"
        : "+f"(c[0]), "+f"(c[1]), "+f"(c[2]), "+f"(c[3])
        : "r"(a[0]), "r"(a[1]), "r"(a[2]), "r"(a[3]), "r"(b[0]), "r"(b[1]));
}
__device__ __forceinline__ void ldsm4(uint32_t& r0, uint32_t& r1, uint32_t& r2, uint32_t& r3,
                                      const uint32_t* p) {
    uint32_t a = (uint32_t)__cvta_generic_to_shared(p);
    asm volatile("ldmatrix.sync.aligned.m8n8.x4.shared.b16 {%0,%1,%2,%3}, [%4];"
                 : "=r"(r0), "=r"(r1), "=r"(r2), "=r"(r3) : "r"(a));
}
__device__ __forceinline__ void cp16(void* smem, const void* g) {
    uint32_t s = (uint32_t)__cvta_generic_to_shared(smem);
    asm volatile("cp.async.cg.shared.global [%0], [%1], 16;\n" :: "r"(s), "l"(g));
}
__device__ __forceinline__ uint64_t mk_evict_last() {
    uint64_t p;
    asm("createpolicy.fractional.L2::evict_last.b64 %0, 1.0;" : "=l"(p));
    return p;
}
__device__ __forceinline__ void cp16_el(void* smem, const void* g, uint64_t pol) {
    uint32_t s = (uint32_t)__cvta_generic_to_shared(smem);
    asm volatile("cp.async.cg.shared.global.L2::cache_hint [%0], [%1], 16, %2;\n"
                 :: "r"(s), "l"(g), "l"(pol));
}
__device__ __forceinline__ void cp_commit() { asm volatile("cp.async.commit_group;\n"); }
__device__ __forceinline__ void cp_wait1()  { asm volatile("cp.async.wait_group 1;\n"); }
__device__ __forceinline__ void cp_wait0()  { asm volatile("cp.async.wait_group 0;\n"); }
__device__ __forceinline__ void prefetchL2(const void* p) {
    asm volatile("prefetch.global.L2 [%0];" :: "l"(p));
}

__device__ __forceinline__ float sigf(float x) { return 1.f / (1.f + __expf(-x)); }
__device__ __forceinline__ float clip3(float v) { return fminf(fmaxf(v, -3.f), 3.f); }
__device__ __forceinline__ void stcs32(__half* p, __half2 v) {
    asm volatile("st.global.cs.b32 [%0], %1;\n" :: "l"(p), "r"(*(uint32_t*)&v));
}

// ------------------------- repack weights + convert x to fp16 -------------------------
__global__ void repack_kernel(const float* __restrict__ x,
                              const float* __restrict__ Wi, const float* __restrict__ Wh,
                              const float* __restrict__ bb, const float* __restrict__ Wp)
{
    size_t stride = (size_t)gridDim.x * blockDim.x;
    size_t tid0 = (size_t)blockIdx.x * blockDim.x + threadIdx.x;

    // layer 0: Wi0 / Wh0, interleaved np = c*4+g, K=512
    const size_t N1 = 2ull * 16384ull * 512ull;
    for (size_t i = tid0; i < N1; i += stride) {
        size_t dir = i >> 23;
        size_t rem = i & ((1ull << 23) - 1);
        int np = (int)(rem >> 9), k = (int)(rem & 511);
        int c = np >> 2, g = np & 3;
        size_t src = (dir << 23) + ((size_t)(g * 4096 + c) << 9) + k;   // ld = dir (layer 0)
        g_Wi0H[i] = __float2half_rn(Wi[src]);
        g_Wh0H[i] = __float2half_rn(Wh[src]);
    }
    // layer 1: Wc1 = [Wh1 | Wi1], K=1024
    const size_t N2 = 2ull * 16384ull * 1024ull;
    for (size_t i = tid0; i < N2; i += stride) {
        size_t dir = i >> 24;
        size_t rem = i & ((1ull << 24) - 1);
        int np = (int)(rem >> 10), k = (int)(rem & 1023);
        int c = np >> 2, g = np & 3;
        size_t ld = 2 + dir;
        if (k < 512) {
            size_t src = (ld << 23) + ((size_t)(g * 4096 + c) << 9) + k;
            g_Wc1H[i] = __float2half_rn(Wh[src]);
        } else {
            size_t src = (ld << 23) + ((size_t)(g * 4096 + c) << 9) + (k - 512);
            g_Wc1H[i] = __float2half_rn(Wi[src]);
        }
    }
    for (size_t i = tid0; i < 4ull * 512ull * 4096ull; i += stride)
        g_WpH[i] = __float2half_rn(Wp[i]);
    for (size_t i = tid0; i < 8192ull * 512ull; i += stride)
        g_xH[i] = __float2half_rn(x[i]);
    for (size_t i = tid0; i < 4ull * 16384ull; i += stride) {
        int ld = (int)(i >> 14), np = (int)(i & 16383);
        int c = np >> 2, g = np & 3;
        g_bQ[i] = bb[(ld << 14) + g * 4096 + c];
    }
}

__global__ void zero_state()
{
    int i0 = blockIdx.x * blockDim.x + threadIdx.x, st = gridDim.x * blockDim.x;
    for (int i = i0; i < 4 * 64 * 4096; i += st) g_c[i] = 0.f;
    for (int i = i0; i < 4 * 64 * 512;  i += st) g_hH[i] = __float2half_rn(0.f);
}

// ------------------------- xproj GEMM for layer 0 only -------------------------
// C[8192,16384] = x[8192,512] @ Wi0^T (+bias). BM=128 BN=128 BK=32(half), 256 thr.
__global__ void __launch_bounds__(256) xproj_kernel()
{
    __shared__ __align__(16) uint32_t As[2][128][20];
    __shared__ __align__(16) uint32_t Bs[2][128][20];
    int dir = blockIdx.z;
    const __half* Bw = g_Wi0H + ((size_t)dir << 23);
    int m0 = blockIdx.y * 128, n0 = blockIdx.x * 128;
    int tid = threadIdx.x, lane = tid & 31, w = tid >> 5;
    int wm = w >> 1, wn = w & 1;
    int g = lane >> 2, t4 = lane & 3;
    int lrow = lane & 15, ktop = (lane >> 4) * 4;
    int bn = ((lane >> 4) << 3) + (lane & 7);
    int bk = ((lane >> 3) & 1) * 4;

    float acc[2][8][4];
#pragma unroll
    for (int a = 0; a < 2; a++)
#pragma unroll
        for (int b = 0; b < 8; b++)
#pragma unroll
            for (int q = 0; q < 4; q++) acc[a][b][q] = 0.f;

    const __half* Ag = g_xH + (size_t)m0 * 512;
    const __half* Bg = Bw + (size_t)n0 * 512;

    auto load = [&](int st, int buf) {
        int k0 = st * 32;
#pragma unroll
        for (int i = 0; i < 2; i++) {
            int idx = tid + 256 * i;
            int r = idx >> 2, q = idx & 3;
            cp16(&As[buf][r][q * 4], Ag + (size_t)r * 512 + k0 + q * 8);
            cp16(&Bs[buf][r][q * 4], Bg + (size_t)r * 512 + k0 + q * 8);
        }
    };

    load(0, 0); cp_commit();
#pragma unroll 1
    for (int st = 0; st < 16; st++) {
        int buf = st & 1;
        if (st + 1 < 16) { load(st + 1, buf ^ 1); cp_commit(); cp_wait1(); }
        else             { cp_wait0(); }
        __syncthreads();
        const uint32_t* Ab = &As[buf][0][0];
        const uint32_t* Bb = &Bs[buf][0][0];
#pragma unroll
        for (int kk = 0; kk < 2; kk++) {
            uint32_t af[2][4], bf[8][2];
#pragma unroll
            for (int mi = 0; mi < 2; mi++)
                ldsm4(af[mi][0], af[mi][1], af[mi][2], af[mi][3],
                      Ab + (wm * 32 + mi * 16 + lrow) * 20 + kk * 8 + ktop);
#pragma unroll
            for (int pr = 0; pr < 4; pr++)
                ldsm4(bf[pr * 2][0], bf[pr * 2][1], bf[pr * 2 + 1][0], bf[pr * 2 + 1][1],
                      Bb + (wn * 64 + pr * 16 + bn) * 20 + kk * 8 + bk);
#pragma unroll
            for (int mi = 0; mi < 2; mi++)
#pragma unroll
                for (int ni = 0; ni < 8; ni++)
                    mmah(acc[mi][ni], af[mi], bf[ni]);
        }
        __syncthreads();
    }

    const float* bias = g_bQ + dir * 16384;
    __half* Co = g_xprojH + (size_t)dir * 8192ull * 16384ull;
#pragma unroll
    for (int mi = 0; mi < 2; mi++) {
        int rm = m0 + wm * 32 + mi * 16 + g;
#pragma unroll
        for (int ni = 0; ni < 8; ni++) {
            int cn = n0 + wn * 64 + ni * 8 + t4 * 2;
            float2 bv = *(const float2*)&bias[cn];
            stcs32(&Co[(size_t)rm * 16384 + cn],
                   __floats2half2_rn(acc[mi][ni][0] + bv.x, acc[mi][ni][1] + bv.y));
            stcs32(&Co[(size_t)(rm + 8) * 16384 + cn],
                   __floats2half2_rn(acc[mi][ni][2] + bv.x, acc[mi][ni][3] + bv.y));
        }
    }
}

// ------------------------- gate slot kernel (both layers pipelined) --------------------
// blockIdx.y = ld (l=ld>>1, dir=ld&1). l0: step=slot, K=512, epi adds xproj slice.
// l1: step=slot-1, K=1024 with A=[h1, y0[t]], epi adds bias. BM=64 BN=128 BK=32, 3-stage.
// __launch_bounds__(256,4): 4 CTAs/SM -> 512-CTA grid fits one wave (cap 592).
#define GATE_SMEM 46080

__global__ void __launch_bounds__(256, 4) gate_kernel(int slot, float* __restrict__ out)
{
    extern __shared__ __align__(16) uint32_t smu[];
    uint32_t* Asm = smu;                 // [3][64][20]
    uint32_t* Bsm = smu + 3 * 64 * 20;   // [3][128][20]

    int ld = blockIdx.y;
    int l = ld >> 1, dir = ld & 1;
    int step = (l == 0) ? slot : slot - 1;
    if (step < 0 || step > 127) return;
    int last = (step == 127) ? 1 : 0;
    int t = dir ? (127 - step) : step;
    int np0 = blockIdx.x * 128;
    int KS = (l == 0) ? 16 : 32;         // BK=32-half stages

    const __half* hA = g_hH + ld * 64 * 512;
    const __half* inA = g_y0H + (size_t)dir * 8192ull * 512ull;   // l1 only
    const __half* Bg = (l == 0)
        ? (g_Wh0H + ((size_t)dir << 23) + (size_t)np0 * 512)
        : (g_Wc1H + ((size_t)dir << 24) + (size_t)np0 * 1024);
    size_t wstride = (l == 0) ? 512 : 1024;
    const __half* xp = g_xprojH + (size_t)dir * 8192ull * 16384ull;
    uint64_t pol = mk_evict_last();

    int tid = threadIdx.x, lane = tid & 31, w = tid >> 5;
    int wm = w >> 2, wn = w & 3;
    int g = lane >> 2, t4 = lane & 3;
    int lrow = lane & 15, ktop = (lane >> 4) * 4;
    int bn = ((lane >> 4) << 3) + (lane & 7);
    int bk = ((lane >> 3) & 1) * 4;

    // prefetch epilogue/input data into L2 early
    if (l == 0) {
        if (tid < 128) {
            int b = tid >> 1, half128 = tid & 1;
            prefetchL2(xp + (size_t)(b * 128 + t) * 16384 + np0 + half128 * 64);
        }
    } else {
        int r = tid >> 2, seg = tid & 3;
        prefetchL2(inA + (size_t)(r * 128 + t) * 512 + seg * 128);
    }

    float acc[2][4][4];
#pragma unroll
    for (int a = 0; a < 2; a++)
#pragma unroll
        for (int b = 0; b < 4; b++)
#pragma unroll
            for (int q = 0; q < 4; q++) acc[a][b][q] = 0.f;

    // Wh0 (32MB) kept L2-resident via evict_last; Wc1 (64MB) streams default policy
    auto load = [&](int st, int buf) {
        int k0 = st * 32;
        {
            int r = tid >> 2, q = tid & 3;
            const __half* src;
            if (k0 < 512) src = hA + (size_t)r * 512 + k0 + q * 8;
            else          src = inA + (size_t)(r * 128 + t) * 512 + (k0 - 512) + q * 8;
            cp16(&Asm[(buf * 64 + r) * 20 + q * 4], src);
        }
#pragma unroll
        for (int i = 0; i < 2; i++) {
            int idx = tid + 256 * i;
            int r = idx >> 2, q = idx & 3;
            const __half* bsrc = Bg + (size_t)r * wstride + k0 + q * 8;
            if (l == 0) cp16_el(&Bsm[(buf * 128 + r) * 20 + q * 4], bsrc, pol);
            else        cp16(&Bsm[(buf * 128 + r) * 20 + q * 4], bsrc);
        }
    };

    load(0, 0); cp_commit();
    load(1, 1); cp_commit();
#pragma unroll 1
    for (int st = 0; st < KS; st++) {
        if (st < KS - 1) cp_wait1(); else cp_wait0();
        __syncthreads();
        if (st + 2 < KS) { load(st + 2, (st + 2) % 3); cp_commit(); }
        int buf = st % 3;
        const uint32_t* Ab = Asm + buf * 64 * 20;
        const uint32_t* Bb = Bsm + buf * 128 * 20;
#pragma unroll
        for (int kk = 0; kk < 2; kk++) {
            uint32_t af[2][4], bf[4][2];
#pragma unroll
            for (int mi = 0; mi < 2; mi++)
                ldsm4(af[mi][0], af[mi][1], af[mi][2], af[mi][3],
                      Ab + (wm * 32 + mi * 16 + lrow) * 20 + kk * 8 + ktop);
#pragma unroll
            for (int pr = 0; pr < 2; pr++)
                ldsm4(bf[pr * 2][0], bf[pr * 2][1], bf[pr * 2 + 1][0], bf[pr * 2 + 1][1],
                      Bb + (wn * 32 + pr * 16 + bn) * 20 + kk * 8 + bk);
#pragma unroll
            for (int mi = 0; mi < 2; mi++)
#pragma unroll
                for (int ni = 0; ni < 4; ni++)
                    mmah(acc[mi][ni], af[mi], bf[ni]);
        }
    }
    __syncthreads();

    float* gsm = (float*)smu;            // [64][132]
#pragma unroll
    for (int mi = 0; mi < 2; mi++) {
        int r = wm * 32 + mi * 16 + g;
#pragma unroll
        for (int ni = 0; ni < 4; ni++) {
            int n = wn * 32 + ni * 8 + t4 * 2;
            gsm[r * 132 + n]           = acc[mi][ni][0];
            gsm[r * 132 + n + 1]       = acc[mi][ni][1];
            gsm[(r + 8) * 132 + n]     = acc[mi][ni][2];
            gsm[(r + 8) * 132 + n + 1] = acc[mi][ni][3];
        }
    }
    __syncthreads();

    const float* bq = g_bQ + ld * 16384;
#pragma unroll 1
    for (int p = 0; p < 4; p++) {
        int idx = p * 256 + tid;
        int q2 = idx & 15, b = idx >> 4;
        float2 x0, x1, x2, x3;
        if (l == 0) {
            const uint4* xr = (const uint4*)(xp + (size_t)(b * 128 + t) * 16384 + np0 + q2 * 8);
            uint4 xv = __ldcs(xr);
            x0 = __half22float2(*(__half2*)&xv.x);
            x1 = __half22float2(*(__half2*)&xv.y);
            x2 = __half22float2(*(__half2*)&xv.z);
            x3 = __half22float2(*(__half2*)&xv.w);
        } else {
            float4 bv0 = *(const float4*)&bq[np0 + q2 * 8];
            float4 bv1 = *(const float4*)&bq[np0 + q2 * 8 + 4];
            x0 = make_float2(bv0.x, bv0.y);
            x1 = make_float2(bv0.z, bv0.w);
            x2 = make_float2(bv1.x, bv1.y);
            x3 = make_float2(bv1.z, bv1.w);
        }
        float4 gA = *(const float4*)&gsm[b * 132 + q2 * 8];
        float4 gB = *(const float4*)&gsm[b * 132 + q2 * 8 + 4];

        int cg0 = (np0 >> 2) + q2 * 2;
        int ci0 = ld * 64 * 4096 + b * 4096 + cg0;
        {
            float ii = sigf(gA.x + x0.x), ff = sigf(gA.y + x0.y);
            float gg = tanhf(gA.z + x1.x), oo = sigf(gA.w + x1.y);
            float cn = clip3(ii * gg + ff * g_c[ci0]);
            g_c[ci0] = cn;
            g_aH[ci0] = __float2half_rn(oo * tanhf(cn));
            if (last)
                out[CS_OFF + (size_t)(l * 64 + b) * 8192 + dir * 4096 + cg0] = cn;
        }
        {
            float ii = sigf(gB.x + x2.x), ff = sigf(gB.y + x2.y);
            float gg = tanhf(gB.z + x3.x), oo = sigf(gB.w + x3.y);
            float cn = clip3(ii * gg + ff * g_c[ci0 + 1]);
            g_c[ci0 + 1] = cn;
            g_aH[ci0 + 1] = __float2half_rn(oo * tanhf(cn));
            if (last)
                out[CS_OFF + (size_t)(l * 64 + b) * 8192 + dir * 4096 + cg0 + 1] = cn;
        }
    }
}

// ------------------------- projection GEMM (split-K) both layers -----------------------
// grid (4 n0, 16 kk, 4 ld). part[ld][kk][64,512] = a[ld][64, kslice] @ Wp[ld]^T
__global__ void __launch_bounds__(256) proj_kernel(int slot)
{
    __shared__ __align__(16) uint32_t As[2][64][20];
    __shared__ __align__(16) uint32_t Bs[2][128][20];
    int ld = blockIdx.z;
    int l = ld >> 1;
    int step = (l == 0) ? slot : slot - 1;
    if (step < 0 || step > 127) return;
    int n0 = blockIdx.x * 128;
    int kk = blockIdx.y;
    int kc0 = kk * 256;

    const __half* Ag = g_aH + ld * 64 * 4096 + kc0;
    const __half* Bg = g_WpH + (size_t)ld * 512 * 4096 + (size_t)n0 * 4096 + kc0;
    uint64_t pol = mk_evict_last();

    int tid = threadIdx.x, lane = tid & 31, w = tid >> 5;
    int wm = w >> 2, wn = w & 3;
    int g = lane >> 2, t4 = lane & 3;
    int lrow = lane & 15, ktop = (lane >> 4) * 4;
    int bn = ((lane >> 4) << 3) + (lane & 7);
    int bk = ((lane >> 3) & 1) * 4;

    float acc[2][4][4];
#pragma unroll
    for (int a = 0; a < 2; a++)
#pragma unroll
        for (int b = 0; b < 4; b++)
#pragma unroll
            for (int q = 0; q < 4; q++) acc[a][b][q] = 0.f;

    auto load = [&](int st, int buf) {
        int k0 = st * 32;
        {
            int r = tid >> 2, q = tid & 3;
            cp16(&As[buf][r][q * 4], Ag + (size_t)r * 4096 + k0 + q * 8);
        }
#pragma unroll
        for (int i = 0; i < 2; i++) {
            int idx = tid + 256 * i;
            int r = idx >> 2, q = idx & 3;
            cp16_el(&Bs[buf][r][q * 4], Bg + (size_t)r * 4096 + k0 + q * 8, pol);
        }
    };

    load(0, 0); cp_commit();
#pragma unroll 1
    for (int st = 0; st < 8; st++) {
        int buf = st & 1;
        if (st + 1 < 8) { load(st + 1, buf ^ 1); cp_commit(); cp_wait1(); }
        else            { cp_wait0(); }
        __syncthreads();
        const uint32_t* Ab = &As[buf][0][0];
        const uint32_t* Bb = &Bs[buf][0][0];
#pragma unroll
        for (int kk2 = 0; kk2 < 2; kk2++) {
            uint32_t af[2][4], bf[4][2];
#pragma unroll
            for (int mi = 0; mi < 2; mi++)
                ldsm4(af[mi][0], af[mi][1], af[mi][2], af[mi][3],
                      Ab + (wm * 32 + mi * 16 + lrow) * 20 + kk2 * 8 + ktop);
#pragma unroll
            for (int pr = 0; pr < 2; pr++)
                ldsm4(bf[pr * 2][0], bf[pr * 2][1], bf[pr * 2 + 1][0], bf[pr * 2 + 1][1],
                      Bb + (wn * 32 + pr * 16 + bn) * 20 + kk2 * 8 + bk);
#pragma unroll
            for (int mi = 0; mi < 2; mi++)
#pragma unroll
                for (int ni = 0; ni < 4; ni++)
                    mmah(acc[mi][ni], af[mi], bf[ni]);
        }
        __syncthreads();
    }

    float* P = g_part + ((size_t)(ld * 16 + kk) * 64) * 512;
#pragma unroll
    for (int mi = 0; mi < 2; mi++) {
        int rm = wm * 32 + mi * 16 + g;
#pragma unroll
        for (int ni = 0; ni < 4; ni++) {
            int cn = n0 + wn * 32 + ni * 8 + t4 * 2;
            *(float2*)&P[(size_t)rm * 512 + cn] =
                make_float2(acc[mi][ni][0], acc[mi][ni][1]);
            *(float2*)&P[(size_t)(rm + 8) * 512 + cn] =
                make_float2(acc[mi][ni][2], acc[mi][ni][3]);
        }
    }
}

// ------------------------- reduce + clip + outputs (both layers) -----------------------
__global__ void reduce_kernel(int slot, float* __restrict__ out)
{
    int e = blockIdx.x * 256 + threadIdx.x;     // 131072 elements
    int ld = e >> 15;
    int l = ld >> 1, dir = ld & 1;
    int step = (l == 0) ? slot : slot - 1;
    if (step < 0 || step > 127) return;
    int last = (step == 127) ? 1 : 0;
    int r = e & 32767;
    int b = r >> 9, j = r & 511;
    int t = dir ? (127 - step) : step;

    const float* p = g_part + (size_t)ld * 16 * 64 * 512 + b * 512 + j;
    float sum = 0.f;
#pragma unroll
    for (int k = 0; k < 16; k++) sum += __ldcg(&p[(size_t)k * 64 * 512]);
    float h = clip3(sum);

    g_hH[ld * 32768 + b * 512 + j] = __float2half_rn(h);

    size_t yi = (size_t)(b * 128 + t) * 512 + j;
    float yv = h;
    if (l == 0) g_y0H[(size_t)dir * 8192ull * 512ull + yi] = __float2half_rn(h);
    else        yv = h + __half2float(g_y0H[(size_t)dir * 8192ull * 512ull + yi]);

    __stcs(&out[SEQ_OFF + ((size_t)(l * 64 + b) * 128 + t) * 1024 + dir * 512 + j], yv);
    if (last)
        __stcs(&out[HS_OFF + (size_t)(l * 64 + b) * 1024 + dir * 512 + j], h);
}

// ------------------------- launch: layer-pipelined slots -------------------------
extern "C" void kernel_launch(void* const* d_in, const int* in_sizes, int n_in,
                              void* d_out, int out_size)
{
    const float* x  = (const float*)d_in[0];
    const float* Wi = (const float*)d_in[1];
    const float* Wh = (const float*)d_in[2];
    const float* bb = (const float*)d_in[3];
    const float* Wp = (const float*)d_in[4];
    float* out = (float*)d_out;

    cudaFuncSetAttribute(gate_kernel,
                         cudaFuncAttributeMaxDynamicSharedMemorySize, GATE_SMEM);

    repack_kernel<<<2048, 256>>>(x, Wi, Wh, bb, Wp);
    zero_state<<<512, 256>>>();
    xproj_kernel<<<dim3(128, 64, 2), 256>>>();

    for (int slot = 0; slot <= 128; slot++) {
        gate_kernel<<<dim3(128, 4), 256, GATE_SMEM>>>(slot, out);
        proj_kernel<<<dim3(4, 16, 4), 256>>>(slot);
        reduce_kernel<<<512, 256>>>(slot, out);
    }
}